// round 5
// baseline (speedup 1.0000x reference)
#include <cuda_runtime.h>
#include <math.h>

#define DIMK 512
#define HD   1024

typedef unsigned long long ull;

// Scratch (device globals). k-split partial results (A: k<256, B: k>=256).
__device__ __align__(16) float g_causA[64 * HD];
__device__ __align__(16) float g_causB[64 * HD];
__device__ __align__(16) float g_effA [64 * HD];
__device__ __align__(16) float g_effB [64 * HD];
__device__ __align__(16) float g_ctxTA[HD * 64];   // transposed [h][b], k-half A
__device__ __align__(16) float g_ctxTB[HD * 64];   // transposed [h][b], k-half B

// ---------------------------------------------------------------------------
// Phase 1: three 64x512 @ 512x1024 GEMMs, all k-split in halves.
// ---------------------------------------------------------------------------
__global__ void __launch_bounds__(256) gemm_kernel(
    const float* __restrict__ state, const float* __restrict__ action,
    const float* __restrict__ embed, const float* __restrict__ W1,
    const float* __restrict__ b1)
{
    const int slot    = blockIdx.y;
    const int colbase = (blockIdx.x >> 1) * 32;
    const int kbase   = (blockIdx.x & 1) * 256;

    const float* W = W1 + slot * DIMK * HD;

    __shared__ float Xs[64][132];

    const int tid = threadIdx.x;
    const int tx  = tid & 15;
    const int ty  = tid >> 4;

    float acc[4][2] = {};

    for (int kt = kbase; kt < kbase + 256; kt += 128) {
        for (int lin = tid; lin < 64 * 32; lin += 256) {
            int row = lin >> 5;
            int q   = lin & 31;
            int gc  = kt + q * 4;
            float4 v;
            if (slot < 2) {
                v = *reinterpret_cast<const float4*>(embed + row * DIMK + gc);
            } else {
                float4 s4 = *reinterpret_cast<const float4*>(state  + row * DIMK + gc);
                float4 a4 = *reinterpret_cast<const float4*>(action + row * DIMK + gc);
                v = make_float4(s4.x + a4.x, s4.y + a4.y, s4.z + a4.z, s4.w + a4.w);
            }
            *reinterpret_cast<float4*>(&Xs[row][q * 4]) = v;
        }
        __syncthreads();

        #pragma unroll 8
        for (int k = 0; k < 128; k++) {
            float2 w = *reinterpret_cast<const float2*>(W + (kt + k) * HD + colbase + 2 * tx);
            #pragma unroll
            for (int r = 0; r < 4; r++) {
                float xv = Xs[ty + 16 * r][k];
                acc[r][0] = fmaf(xv, w.x, acc[r][0]);
                acc[r][1] = fmaf(xv, w.y, acc[r][1]);
            }
        }
        __syncthreads();
    }

    const int isA = (kbase == 0);
    #pragma unroll
    for (int r = 0; r < 4; r++) {
        int row = ty + 16 * r;
        int c0  = colbase + 2 * tx;
        if (slot == 0) {
            float v0 = acc[r][0], v1 = acc[r][1];
            if (isA) { v0 += b1[c0]; v1 += b1[c0 + 1]; }
            float* dst = isA ? g_causA : g_causB;
            dst[row * HD + c0]     = v0;
            dst[row * HD + c0 + 1] = v1;
        } else if (slot == 1) {
            float* dst = isA ? g_effA : g_effB;
            dst[row * HD + c0]     = acc[r][0];
            dst[row * HD + c0 + 1] = acc[r][1];
        } else {
            float* dst = isA ? g_ctxTA : g_ctxTB;
            dst[c0 * 64 + row]       = acc[r][0];
            dst[(c0 + 1) * 64 + row] = acc[r][1];
        }
    }
}

// ---------------------------------------------------------------------------
// f32x2 packed helpers
// ---------------------------------------------------------------------------
__device__ __forceinline__ ull pack2(float a, float b) {
    ull r;
    asm("mov.b64 %0, {%1, %2};" : "=l"(r)
        : "r"(__float_as_uint(a)), "r"(__float_as_uint(b)));
    return r;
}
__device__ __forceinline__ void unpack2(ull v, float& a, float& b) {
    unsigned int x, y;
    asm("mov.b64 {%0, %1}, %2;" : "=r"(x), "=r"(y) : "l"(v));
    a = __uint_as_float(x); b = __uint_as_float(y);
}
__device__ __forceinline__ ull add2(ull a, ull b) {
    ull r; asm("add.rn.f32x2 %0, %1, %2;" : "=l"(r) : "l"(a), "l"(b)); return r;
}
__device__ __forceinline__ ull mul2(ull a, ull b) {
    ull r; asm("mul.rn.f32x2 %0, %1, %2;" : "=l"(r) : "l"(a), "l"(b)); return r;
}
__device__ __forceinline__ ull fma2(ull a, ull b, ull c) {
    ull r; asm("fma.rn.f32x2 %0, %1, %2, %3;" : "=l"(r) : "l"(a), "l"(b), "l"(c)); return r;
}
// packed f16x2 tanh of a packed f32x2 value: lo->lo, hi->hi
__device__ __forceinline__ ull tanh2_f16(ull in2) {
    float ia, ib; unpack2(in2, ia, ib);
    unsigned int h2, th2;
    asm("cvt.rn.f16x2.f32 %0, %1, %2;" : "=r"(h2) : "f"(ib), "f"(ia)); // hi=ib, lo=ia
    asm("tanh.approx.f16x2 %0, %1;" : "=r"(th2) : "r"(h2));
    float t0, t1;
    asm("{\n\t.reg .b16 l, h;\n\tmov.b32 {l, h}, %2;\n\t"
        "cvt.f32.f16 %0, l;\n\tcvt.f32.f16 %1, h;\n\t}"
        : "=f"(t0), "=f"(t1) : "r"(th2));
    return pack2(t0, t1);
}

// ---------------------------------------------------------------------------
// Phase 2: scores[i,j] = mean_b sigmoid( sum_h gelu(ctx+caus+eff)*W2 + b2 )
// Same schedule as R3 (512 blocks x 8 warps, warp=pair, lane=b-pair),
// but the two tanh per lane-k collapse into ONE tanh.approx.f16x2 (MUFU).
// ---------------------------------------------------------------------------
__global__ void __launch_bounds__(256) score_kernel(
    const float* __restrict__ W2, const float* __restrict__ b2,
    float* __restrict__ out)
{
    extern __shared__ float sm[];
    float* caus_s = sm;              // 2 * 1024
    float* eff_s  = sm + 2048;       // 4 * 1024
    float* w2p    = sm + 6144;       // 2048 (1024 pairs, pre-halved, duplicated)
    float* ctx_s  = sm + 8192;       // 64 * 64

    const int tid = threadIdx.x;
    const int i0  = (blockIdx.x >> 4) * 2;   // 32 i-tiles
    const int j0  = (blockIdx.x & 15) * 4;   // 16 j-tiles

    for (int lin = tid; lin < 2048; lin += 256) {
        int r = lin >> 10, c = lin & 1023;
        caus_s[lin] = g_causA[(i0 + r) * HD + c] + g_causB[(i0 + r) * HD + c];
    }
    for (int lin = tid; lin < 4096; lin += 256) {
        int r = lin >> 10, c = lin & 1023;
        eff_s[lin]  = g_effA[(j0 + r) * HD + c] + g_effB[(j0 + r) * HD + c];
    }
    for (int lin = tid; lin < 1024; lin += 256) {
        float v = 0.5f * W2[lin];
        w2p[2 * lin]     = v;
        w2p[2 * lin + 1] = v;
    }

    const int w    = tid >> 5;
    const int lane = tid & 31;
    const int wi   = w >> 2, wj = w & 3;
    const float* cs = caus_s + wi * 1024;
    const float* es = eff_s  + wj * 1024;
    const ull*  ctxp = reinterpret_cast<const ull*>(ctx_s);

    const ull C0 = pack2(0.7978845608f, 0.7978845608f);
    const ull C1 = pack2(0.0356774081f, 0.0356774081f);
    ull accL = pack2(0.f, 0.f);
    ull accT = pack2(0.f, 0.f);

    for (int ht = 0; ht < HD; ht += 64) {
        __syncthreads();   // covers initial staging on first iter
        for (int lin = tid * 4; lin < 64 * 64; lin += 256 * 4) {
            float4 a4 = *reinterpret_cast<const float4*>(g_ctxTA + ht * 64 + lin);
            float4 b4 = *reinterpret_cast<const float4*>(g_ctxTB + ht * 64 + lin);
            *reinterpret_cast<float4*>(ctx_s + lin) =
                make_float4(a4.x + b4.x, a4.y + b4.y, a4.z + b4.z, a4.w + b4.w);
        }
        __syncthreads();

        const float* w2row = w2p + 2 * ht;
        #pragma unroll 4
        for (int k = 0; k < 64; k += 4) {
            float4 cv = *reinterpret_cast<const float4*>(cs + ht + k);
            float4 ev = *reinterpret_cast<const float4*>(es + ht + k);
            float ce[4] = {cv.x + ev.x, cv.y + ev.y, cv.z + ev.z, cv.w + ev.w};
            #pragma unroll
            for (int q = 0; q < 4; q++) {
                ull ce2 = pack2(ce[q], ce[q]);
                ull hw2 = *reinterpret_cast<const ull*>(w2row + 2 * (k + q));
                ull c2  = ctxp[(k + q) * 32 + lane];
                ull x2  = add2(ce2, c2);
                ull u2  = mul2(x2, x2);
                ull p2  = fma2(u2, C1, C0);
                ull in2 = mul2(x2, p2);
                ull t2  = tanh2_f16(in2);          // ONE MUFU op for both batches
                ull xw2 = mul2(x2, hw2);
                accL = add2(accL, xw2);
                accT = fma2(xw2, t2, accT);
            }
        }
    }

    ull acc = add2(accL, accT);
    float a0, a1; unpack2(acc, a0, a1);
    float bb = b2[0];
    float s = 1.0f / (1.0f + expf(-(a0 + bb)))
            + 1.0f / (1.0f + expf(-(a1 + bb)));
    #pragma unroll
    for (int off = 16; off; off >>= 1)
        s += __shfl_down_sync(0xffffffffu, s, off);
    if (lane == 0)
        out[(i0 + wi) * 64 + (j0 + wj)] = s * (1.0f / 64.0f);
}

// ---------------------------------------------------------------------------
extern "C" void kernel_launch(void* const* d_in, const int* in_sizes, int n_in,
                              void* d_out, int out_size)
{
    const float* state  = (const float*)d_in[0];
    const float* action = (const float*)d_in[1];
    const float* embed  = (const float*)d_in[2];
    const float* W1     = (const float*)d_in[3];
    const float* b1     = (const float*)d_in[4];
    const float* W2     = (const float*)d_in[5];
    const float* b2     = (const float*)d_in[6];
    float* out = (float*)d_out;

    dim3 g1(64, 3);
    gemm_kernel<<<g1, 256>>>(state, action, embed, W1, b1);

    const int smem = (2048 + 4096 + 2048 + 4096) * sizeof(float); // 49152 B
    cudaFuncSetAttribute(score_kernel, cudaFuncAttributeMaxDynamicSharedMemorySize, smem);
    score_kernel<<<512, 256, smem>>>(W2, b2, out);
}